// round 8
// baseline (speedup 1.0000x reference)
#include <cuda_runtime.h>
#include <cuda_fp16.h>
#include <math.h>

// DistributionLoss: local 7x7x3 std of two [16,3,512,512] f32 tensors,
// smooth-L1 between std maps, global mean.
//
// R8: stall attack round 2. Separate hsum smem buffer (no in-place passes)
// -> 4 barriers/block. Register diet (sequential strip accumulation, early
// half2 conversion) + launch_bounds(256,7) -> 87.5% occ ceiling.

#define TW    64
#define TH    16
#define HALO  3
#define HR    22                  // halo rows  (TH + 6)
#define WC    70                  // halo cols  (TW + 6)
#define RPITCH 74                 // s_raw pitch in 8B cells (max swizzled 73)
#define HPITCH 68                 // s_hs  pitch in 8B cells (max swizzled 66)
#define NINV  (1.0f / 147.0f)
#define EPS   1e-8f
#define HWSZ  (512 * 512)
#define NPIX  (16.0f * 512.0f * 512.0f)
#define NBLK  4096                // 8 x 32 x 16

// 8B-cell swizzle: injective, distinct mod 16 for stride-4 and stride-1.
#define SWC(c) ((c) + ((c) >> 4))

__device__ float        g_partials[NBLK];
__device__ unsigned int g_count;   // zero-init; self-resets via atomicInc wrap

struct Cell { __half2 p, t; };     // (s, s2) for pred / tgt

__device__ __forceinline__ Cell u2c(uint2 v) {
    Cell c;
    c.p = *reinterpret_cast<__half2*>(&v.x);
    c.t = *reinterpret_cast<__half2*>(&v.y);
    return c;
}
__device__ __forceinline__ uint2 c2u(Cell c) {
    uint2 v;
    v.x = *reinterpret_cast<unsigned int*>(&c.p);
    v.y = *reinterpret_cast<unsigned int*>(&c.t);
    return v;
}
__device__ __forceinline__ Cell cadd(Cell a, Cell b) {
    Cell r; r.p = __hadd2(a.p, b.p); r.t = __hadd2(a.t, b.t); return r;
}
__device__ __forceinline__ Cell cslide(Cell w, Cell in, Cell out) {
    Cell r;
    r.p = __hadd2(w.p, __hsub2(in.p, out.p));
    r.t = __hadd2(w.t, __hsub2(in.t, out.t));
    return r;
}

__global__ __launch_bounds__(256, 7)
void dist_loss_main(const float* __restrict__ pred,
                    const float* __restrict__ tgt,
                    float* __restrict__ out)
{
    __shared__ uint2 s_raw[HR * RPITCH];   // channel-summed (s,s2) cells
    __shared__ uint2 s_hs [HR * HPITCH];   // horizontal 7-sums
    __shared__ float s_warp[8];
    __shared__ bool  s_is_last;

    const int tid  = threadIdx.y * 32 + threadIdx.x;
    const int lane = threadIdx.x;
    const int wid  = threadIdx.y;
    const int x0   = blockIdx.x * TW;
    const int y0   = blockIdx.y * TH;

    const float* p  = pred + (size_t)blockIdx.z * 3 * HWSZ;
    const float* tg = tgt  + (size_t)blockIdx.z * 3 * HWSZ;

    // ---- Phase 1: 396 tasks = 22 rows x 18 float4 col-groups ----
    // Pred converted to half2 before tgt loads -> lower register peak.
    for (int task = tid; task < HR * 18; task += 256) {
        int r   = task / 18;
        int g   = task - r * 18;
        int gy  = y0 - HALO + r;
        int gx0 = x0 - 4 + 4 * g;
        bool rowok = ((unsigned)gy < 512u);

        __half2 hp[4], ht[4];
        if (rowok && gx0 >= 0 && gx0 <= 508) {
            size_t off = (size_t)gy * 512 + gx0;
            {
                float4 a0 = *(const float4*)(p + off);
                float4 a1 = *(const float4*)(p + HWSZ + off);
                float4 a2 = *(const float4*)(p + 2 * HWSZ + off);
                hp[0] = __floats2half2_rn(a0.x + a1.x + a2.x, a0.x*a0.x + a1.x*a1.x + a2.x*a2.x);
                hp[1] = __floats2half2_rn(a0.y + a1.y + a2.y, a0.y*a0.y + a1.y*a1.y + a2.y*a2.y);
                hp[2] = __floats2half2_rn(a0.z + a1.z + a2.z, a0.z*a0.z + a1.z*a1.z + a2.z*a2.z);
                hp[3] = __floats2half2_rn(a0.w + a1.w + a2.w, a0.w*a0.w + a1.w*a1.w + a2.w*a2.w);
            }
            {
                float4 b0 = *(const float4*)(tg + off);
                float4 b1 = *(const float4*)(tg + HWSZ + off);
                float4 b2 = *(const float4*)(tg + 2 * HWSZ + off);
                ht[0] = __floats2half2_rn(b0.x + b1.x + b2.x, b0.x*b0.x + b1.x*b1.x + b2.x*b2.x);
                ht[1] = __floats2half2_rn(b0.y + b1.y + b2.y, b0.y*b0.y + b1.y*b1.y + b2.y*b2.y);
                ht[2] = __floats2half2_rn(b0.z + b1.z + b2.z, b0.z*b0.z + b1.z*b1.z + b2.z*b2.z);
                ht[3] = __floats2half2_rn(b0.w + b1.w + b2.w, b0.w*b0.w + b1.w*b1.w + b2.w*b2.w);
            }
        } else {
#pragma unroll
            for (int j = 0; j < 4; j++) {
                int gx = gx0 + j;
                float v0 = 0.f, v1 = 0.f, v2 = 0.f;
                float w0 = 0.f, w1 = 0.f, w2 = 0.f;
                if (rowok && ((unsigned)gx < 512u)) {
                    size_t off = (size_t)gy * 512 + gx;
                    v0 = p[off];  v1 = p[HWSZ + off];  v2 = p[2 * HWSZ + off];
                    w0 = tg[off]; w1 = tg[HWSZ + off]; w2 = tg[2 * HWSZ + off];
                }
                hp[j] = __floats2half2_rn(v0 + v1 + v2, v0*v0 + v1*v1 + v2*v2);
                ht[j] = __floats2half2_rn(w0 + w1 + w2, w0*w0 + w1*w1 + w2*w2);
            }
        }
#pragma unroll
        for (int j = 0; j < 4; j++) {
            int c = 4 * g + j - 1;
            if ((unsigned)c < (unsigned)WC) {
                Cell cl; cl.p = hp[j]; cl.t = ht[j];
                s_raw[r * RPITCH + SWC(c)] = c2u(cl);
            }
        }
    }
    __syncthreads();                                           // B1

    // ---- Phase 2: horizontal 7-sum -> s_hs; sequential accumulation ----
    // 352 tasks = 22 rows x 16 groups of 4 output cols.
    for (int task = tid; task < HR * 16; task += 256) {
        int r  = task >> 4;
        int g2 = task & 15;
        const uint2* row = s_raw + r * RPITCH;
        uint2* hrow = s_hs + r * HPITCH;
        const int cb = 4 * g2;

        Cell e0 = u2c(row[SWC(cb + 0)]);
        Cell e1 = u2c(row[SWC(cb + 1)]);
        Cell e2 = u2c(row[SWC(cb + 2)]);
        Cell w  = cadd(cadd(e0, e1), e2);
        w = cadd(w, u2c(row[SWC(cb + 3)]));
        w = cadd(w, u2c(row[SWC(cb + 4)]));
        w = cadd(w, u2c(row[SWC(cb + 5)]));
        w = cadd(w, u2c(row[SWC(cb + 6)]));
        hrow[SWC(cb + 0)] = c2u(w);
        w = cslide(w, u2c(row[SWC(cb + 7)]), e0);
        hrow[SWC(cb + 1)] = c2u(w);
        w = cslide(w, u2c(row[SWC(cb + 8)]), e1);
        hrow[SWC(cb + 2)] = c2u(w);
        w = cslide(w, u2c(row[SWC(cb + 9)]), e2);
        hrow[SWC(cb + 3)] = c2u(w);
    }
    __syncthreads();                                           // B2

    // ---- Phase 3: vertical 7-sum (half2) + std + smooth-L1 (fp32) ----
    float acc = 0.f;
    {
        const int c3 = tid & 63;     // output col 0..63
        const int rg = tid >> 6;     // 0..3 -> output rows 4rg..4rg+3
        const uint2* col = s_hs + SWC(c3);
        const int rb = rg * 4;

        Cell v0 = u2c(col[(rb + 0) * HPITCH]);
        Cell v1 = u2c(col[(rb + 1) * HPITCH]);
        Cell v2 = u2c(col[(rb + 2) * HPITCH]);
        Cell w  = cadd(cadd(v0, v1), v2);
        w = cadd(w, u2c(col[(rb + 3) * HPITCH]));
        w = cadd(w, u2c(col[(rb + 4) * HPITCH]));
        w = cadd(w, u2c(col[(rb + 5) * HPITCH]));
        w = cadd(w, u2c(col[(rb + 6) * HPITCH]));

#pragma unroll
        for (int q = 0; q < 4; q++) {
            float2 fp = __half22float2(w.p);   // (S, S2) pred
            float2 ft = __half22float2(w.t);   // (S, S2) tgt
            float mup  = fp.x * NINV;
            float varp = fp.y * NINV - mup * mup;
            float sdp  = sqrtf(varp + EPS);
            float mut  = ft.x * NINV;
            float vart = ft.y * NINV - mut * mut;
            float sdt  = sqrtf(vart + EPS);
            float d  = sdp - sdt;
            float ad = fabsf(d);
            acc += (ad < 1.0f) ? 0.5f * d * d : (ad - 0.5f);
            if (q == 0) { w = cslide(w, u2c(col[(rb + 7) * HPITCH]), v0); }
            if (q == 1) { w = cslide(w, u2c(col[(rb + 8) * HPITCH]), v1); }
            if (q == 2) { w = cslide(w, u2c(col[(rb + 9) * HPITCH]), v2); }
        }
    }

    // ---- block reduction: warp shuffle + one barrier ----
#pragma unroll
    for (int off = 16; off > 0; off >>= 1)
        acc += __shfl_down_sync(0xffffffffu, acc, off);
    if (lane == 0) s_warp[wid] = acc;
    __syncthreads();                                           // B3

    const int pidx = blockIdx.z * 256 + blockIdx.y * 8 + blockIdx.x;
    if (wid == 0) {
        float a = (lane < 8) ? s_warp[lane] : 0.f;
#pragma unroll
        for (int off = 4; off > 0; off >>= 1)
            a += __shfl_down_sync(0xffffffffu, a, off);
        if (lane == 0) {
            g_partials[pidx] = a;
            __threadfence();
            unsigned int prev = atomicInc(&g_count, NBLK - 1);  // wraps to 0
            s_is_last = (prev == NBLK - 1);
        }
    }
    __syncthreads();                                           // B4

    // ---- last block: final deterministic reduction ----
    if (s_is_last) {
        float a = 0.f;
#pragma unroll
        for (int i = 0; i < NBLK / 256; i++)
            a += g_partials[tid + i * 256];
#pragma unroll
        for (int off = 16; off > 0; off >>= 1)
            a += __shfl_down_sync(0xffffffffu, a, off);
        if (lane == 0) s_warp[wid] = a;
        __syncthreads();
        if (tid == 0) {
            float s = 0.f;
#pragma unroll
            for (int i = 0; i < 8; i++) s += s_warp[i];
            out[0] = s * (1.0f / NPIX);
        }
    }
}

extern "C" void kernel_launch(void* const* d_in, const int* in_sizes, int n_in,
                              void* d_out, int out_size)
{
    const float* pred = (const float*)d_in[0];
    const float* tgt  = (const float*)d_in[1];
    float* out = (float*)d_out;

    dim3 grid(8, 32, 16);   // x tiles (64 wide), y tiles (16 tall), batch
    dim3 block(32, 8);
    dist_loss_main<<<grid, block>>>(pred, tgt, out);
}

// round 9
// speedup vs baseline: 1.5000x; 1.5000x over previous
#include <cuda_runtime.h>
#include <cuda_fp16.h>
#include <math.h>

// DistributionLoss: local 7x7x3 std of two [16,3,512,512] f32 tensors,
// smooth-L1 between std maps, global mean.
//
// R9: R8 structure (separate hsum buffer, 4 barriers) WITHOUT the register
// squeeze that caused spills (launch_bounds(256,6), ~40 regs, 70% occ).
// fp16 smem cells, half2 SIMD sliding sums, deterministic fused reduction.

#define TW    64
#define TH    16
#define HALO  3
#define HR    22                  // halo rows  (TH + 6)
#define WC    70                  // halo cols  (TW + 6)
#define RPITCH 74                 // s_raw pitch in 8B cells (max swizzled 73)
#define HPITCH 68                 // s_hs  pitch in 8B cells (max swizzled 66)
#define NINV  (1.0f / 147.0f)
#define EPS   1e-8f
#define HWSZ  (512 * 512)
#define NPIX  (16.0f * 512.0f * 512.0f)
#define NBLK  4096                // 8 x 32 x 16

// 8B-cell swizzle: injective, distinct mod 16 for stride-4 and stride-1.
#define SWC(c) ((c) + ((c) >> 4))

__device__ float        g_partials[NBLK];
__device__ unsigned int g_count;   // zero-init; self-resets via atomicInc wrap

struct Cell { __half2 p, t; };     // (s, s2) for pred / tgt

__device__ __forceinline__ Cell u2c(uint2 v) {
    Cell c;
    c.p = *reinterpret_cast<__half2*>(&v.x);
    c.t = *reinterpret_cast<__half2*>(&v.y);
    return c;
}
__device__ __forceinline__ uint2 c2u(Cell c) {
    uint2 v;
    v.x = *reinterpret_cast<unsigned int*>(&c.p);
    v.y = *reinterpret_cast<unsigned int*>(&c.t);
    return v;
}
__device__ __forceinline__ Cell cadd(Cell a, Cell b) {
    Cell r; r.p = __hadd2(a.p, b.p); r.t = __hadd2(a.t, b.t); return r;
}
__device__ __forceinline__ Cell cslide(Cell w, Cell in, Cell out) {
    Cell r;
    r.p = __hadd2(w.p, __hsub2(in.p, out.p));
    r.t = __hadd2(w.t, __hsub2(in.t, out.t));
    return r;
}

__global__ __launch_bounds__(256, 6)
void dist_loss_main(const float* __restrict__ pred,
                    const float* __restrict__ tgt,
                    float* __restrict__ out)
{
    __shared__ uint2 s_raw[HR * RPITCH];   // channel-summed (s,s2) cells
    __shared__ uint2 s_hs [HR * HPITCH];   // horizontal 7-sums
    __shared__ float s_warp[8];
    __shared__ bool  s_is_last;

    const int tid  = threadIdx.y * 32 + threadIdx.x;
    const int lane = threadIdx.x;
    const int wid  = threadIdx.y;
    const int x0   = blockIdx.x * TW;
    const int y0   = blockIdx.y * TH;

    const float* p  = pred + (size_t)blockIdx.z * 3 * HWSZ;
    const float* tg = tgt  + (size_t)blockIdx.z * 3 * HWSZ;

    // ---- Phase 1: 396 tasks = 22 rows x 18 float4 col-groups ----
    for (int task = tid; task < HR * 18; task += 256) {
        int r   = task / 18;
        int g   = task - r * 18;
        int gy  = y0 - HALO + r;
        int gx0 = x0 - 4 + 4 * g;
        bool rowok = ((unsigned)gy < 512u);

        __half2 hp[4], ht[4];
        if (rowok && gx0 >= 0 && gx0 <= 508) {
            size_t off = (size_t)gy * 512 + gx0;
            float4 a0 = *(const float4*)(p + off);
            float4 a1 = *(const float4*)(p + HWSZ + off);
            float4 a2 = *(const float4*)(p + 2 * HWSZ + off);
            float4 b0 = *(const float4*)(tg + off);
            float4 b1 = *(const float4*)(tg + HWSZ + off);
            float4 b2 = *(const float4*)(tg + 2 * HWSZ + off);
            hp[0] = __floats2half2_rn(a0.x + a1.x + a2.x, a0.x*a0.x + a1.x*a1.x + a2.x*a2.x);
            hp[1] = __floats2half2_rn(a0.y + a1.y + a2.y, a0.y*a0.y + a1.y*a1.y + a2.y*a2.y);
            hp[2] = __floats2half2_rn(a0.z + a1.z + a2.z, a0.z*a0.z + a1.z*a1.z + a2.z*a2.z);
            hp[3] = __floats2half2_rn(a0.w + a1.w + a2.w, a0.w*a0.w + a1.w*a1.w + a2.w*a2.w);
            ht[0] = __floats2half2_rn(b0.x + b1.x + b2.x, b0.x*b0.x + b1.x*b1.x + b2.x*b2.x);
            ht[1] = __floats2half2_rn(b0.y + b1.y + b2.y, b0.y*b0.y + b1.y*b1.y + b2.y*b2.y);
            ht[2] = __floats2half2_rn(b0.z + b1.z + b2.z, b0.z*b0.z + b1.z*b1.z + b2.z*b2.z);
            ht[3] = __floats2half2_rn(b0.w + b1.w + b2.w, b0.w*b0.w + b1.w*b1.w + b2.w*b2.w);
        } else {
#pragma unroll
            for (int j = 0; j < 4; j++) {
                int gx = gx0 + j;
                float v0 = 0.f, v1 = 0.f, v2 = 0.f;
                float w0 = 0.f, w1 = 0.f, w2 = 0.f;
                if (rowok && ((unsigned)gx < 512u)) {
                    size_t off = (size_t)gy * 512 + gx;
                    v0 = p[off];  v1 = p[HWSZ + off];  v2 = p[2 * HWSZ + off];
                    w0 = tg[off]; w1 = tg[HWSZ + off]; w2 = tg[2 * HWSZ + off];
                }
                hp[j] = __floats2half2_rn(v0 + v1 + v2, v0*v0 + v1*v1 + v2*v2);
                ht[j] = __floats2half2_rn(w0 + w1 + w2, w0*w0 + w1*w1 + w2*w2);
            }
        }
#pragma unroll
        for (int j = 0; j < 4; j++) {
            int c = 4 * g + j - 1;
            if ((unsigned)c < (unsigned)WC) {
                Cell cl; cl.p = hp[j]; cl.t = ht[j];
                s_raw[r * RPITCH + SWC(c)] = c2u(cl);
            }
        }
    }
    __syncthreads();                                           // B1

    // ---- Phase 2: horizontal 7-sum -> s_hs ----
    // 352 tasks = 22 rows x 16 groups; fixed (g2, r2) mapping with hoisted
    // swizzled offsets; rows 16..21 done by the low 96 threads in pass 2.
    {
        const int g2 = tid & 15;     // output cols 4*g2 .. 4*g2+3
        const int r2 = tid >> 4;     // 0..15
        int o[10];
#pragma unroll
        for (int i = 0; i < 10; i++) o[i] = SWC(4 * g2 + i);

#pragma unroll
        for (int pss = 0; pss < 2; pss++) {
            int r = pss * 16 + r2;
            if (r < HR) {
                const uint2* row = s_raw + r * RPITCH;
                uint2* hrow = s_hs + r * HPITCH;
                Cell e0 = u2c(row[o[0]]);
                Cell e1 = u2c(row[o[1]]);
                Cell e2 = u2c(row[o[2]]);
                Cell w  = cadd(cadd(e0, e1), e2);
                w = cadd(w, u2c(row[o[3]]));
                w = cadd(w, u2c(row[o[4]]));
                w = cadd(w, u2c(row[o[5]]));
                w = cadd(w, u2c(row[o[6]]));
                hrow[o[0]] = c2u(w);
                w = cslide(w, u2c(row[o[7]]), e0);
                hrow[o[1]] = c2u(w);
                w = cslide(w, u2c(row[o[8]]), e1);
                hrow[o[2]] = c2u(w);
                w = cslide(w, u2c(row[o[9]]), e2);
                hrow[o[3]] = c2u(w);
            }
        }
    }
    __syncthreads();                                           // B2

    // ---- Phase 3: vertical 7-sum (half2) + std + smooth-L1 (fp32) ----
    float acc = 0.f;
    {
        const int c3 = tid & 63;     // output col 0..63
        const int rg = tid >> 6;     // 0..3 -> output rows 4rg..4rg+3
        const uint2* col = s_hs + SWC(c3);
        const int rb = rg * 4;

        Cell v0 = u2c(col[(rb + 0) * HPITCH]);
        Cell v1 = u2c(col[(rb + 1) * HPITCH]);
        Cell v2 = u2c(col[(rb + 2) * HPITCH]);
        Cell w  = cadd(cadd(v0, v1), v2);
        w = cadd(w, u2c(col[(rb + 3) * HPITCH]));
        w = cadd(w, u2c(col[(rb + 4) * HPITCH]));
        w = cadd(w, u2c(col[(rb + 5) * HPITCH]));
        w = cadd(w, u2c(col[(rb + 6) * HPITCH]));

#pragma unroll
        for (int q = 0; q < 4; q++) {
            float2 fp = __half22float2(w.p);   // (S, S2) pred
            float2 ft = __half22float2(w.t);   // (S, S2) tgt
            float mup  = fp.x * NINV;
            float varp = fp.y * NINV - mup * mup;
            float sdp  = sqrtf(varp + EPS);
            float mut  = ft.x * NINV;
            float vart = ft.y * NINV - mut * mut;
            float sdt  = sqrtf(vart + EPS);
            float d  = sdp - sdt;
            float ad = fabsf(d);
            acc += (ad < 1.0f) ? 0.5f * d * d : (ad - 0.5f);
            if (q == 0) { w = cslide(w, u2c(col[(rb + 7) * HPITCH]), v0); }
            if (q == 1) { w = cslide(w, u2c(col[(rb + 8) * HPITCH]), v1); }
            if (q == 2) { w = cslide(w, u2c(col[(rb + 9) * HPITCH]), v2); }
        }
    }

    // ---- block reduction: warp shuffle + one barrier ----
#pragma unroll
    for (int off = 16; off > 0; off >>= 1)
        acc += __shfl_down_sync(0xffffffffu, acc, off);
    if (lane == 0) s_warp[wid] = acc;
    __syncthreads();                                           // B3

    const int pidx = blockIdx.z * 256 + blockIdx.y * 8 + blockIdx.x;
    if (wid == 0) {
        float a = (lane < 8) ? s_warp[lane] : 0.f;
#pragma unroll
        for (int off = 4; off > 0; off >>= 1)
            a += __shfl_down_sync(0xffffffffu, a, off);
        if (lane == 0) {
            g_partials[pidx] = a;
            __threadfence();
            unsigned int prev = atomicInc(&g_count, NBLK - 1);  // wraps to 0
            s_is_last = (prev == NBLK - 1);
        }
    }
    __syncthreads();                                           // B4

    // ---- last block: final deterministic reduction ----
    if (s_is_last) {
        float a = 0.f;
#pragma unroll
        for (int i = 0; i < NBLK / 256; i++)
            a += g_partials[tid + i * 256];
#pragma unroll
        for (int off = 16; off > 0; off >>= 1)
            a += __shfl_down_sync(0xffffffffu, a, off);
        if (lane == 0) s_warp[wid] = a;
        __syncthreads();
        if (tid == 0) {
            float s = 0.f;
#pragma unroll
            for (int i = 0; i < 8; i++) s += s_warp[i];
            out[0] = s * (1.0f / NPIX);
        }
    }
}

extern "C" void kernel_launch(void* const* d_in, const int* in_sizes, int n_in,
                              void* d_out, int out_size)
{
    const float* pred = (const float*)d_in[0];
    const float* tgt  = (const float*)d_in[1];
    float* out = (float*)d_out;

    dim3 grid(8, 32, 16);   // x tiles (64 wide), y tiles (16 tall), batch
    dim3 block(32, 8);
    dist_loss_main<<<grid, block>>>(pred, tgt, out);
}